// round 16
// baseline (speedup 1.0000x reference)
#include <cuda_runtime.h>
#include <cuda_bf16.h>
#include <math.h>
#include <stdint.h>

// ---------------------------------------------------------------------------
// S2ConvNetModified pipeline.
// R16: GEMM1 (h1 @ D1_to^T, 36 G-MAC dense) replaced by the separable SO(3)
// synthesis (2.8 G-MAC fp32): D^l(a,b,g) = Rz(a) d^l(b) Rz(g), with the
// d-table extracted exactly from D1_to rows at a=g=0. GEMM2/GEMM3 stay on
// bf16x3 mma.sync.
// ---------------------------------------------------------------------------

#define ACT_CST 1.4142135623730951f

// ----- scratch (device globals; no runtime allocation allowed) -------------
__device__ float g_c[32 * 121];
__device__ float g_psi1[20 * 121];
__device__ float g_xT[32 * 9216];
__device__ float g_h1[640 * 1771];                                     // fp32 Fourier coeffs
__device__ __align__(16) __nv_bfloat16 g_Gb[(size_t)640 * 64000];      // [hi|lo] Kp=32000
__device__ __align__(16) __nv_bfloat16 g_Fb[(size_t)384 * 64000];      // [hi|lo] F1_from
__device__ __align__(16) __nv_bfloat16 g_D2b[(size_t)6912 * 576];      // [hi|lo] D2_to Kp=288
__device__ __align__(16) __nv_bfloat16 g_h3b[1280 * 576];              // [hi|lo] Kp=288
__device__ float g_h2[640 * 286];
__device__ float g_psi2[800 * 286];

__constant__ int OFF1c[12] = {0, 1, 10, 35, 84, 165, 286, 455, 680, 969, 1330, 1771};
__constant__ int OFF2c[7]  = {0, 1, 10, 35, 84, 165, 286};

// ----------------------------- helpers -------------------------------------
__device__ __forceinline__ uint32_t smem_u32(const void* p) {
    uint32_t a;
    asm("{ .reg .u64 t; cvta.to.shared.u64 t, %1; cvt.u32.u64 %0, t; }"
        : "=r"(a) : "l"(p));
    return a;
}
__device__ __forceinline__ void cp16(uint32_t dst, const void* src) {
    asm volatile("cp.async.cg.shared.global [%0], [%1], 16;" :: "r"(dst), "l"(src));
}
#define CP_COMMIT() asm volatile("cp.async.commit_group;" ::: "memory")
#define CP_WAIT1()  asm volatile("cp.async.wait_group 1;" ::: "memory")
#define CP_WAIT0()  asm volatile("cp.async.wait_group 0;" ::: "memory")

__device__ __forceinline__ void mma16816(float* c, const uint32_t* a, const uint32_t* b) {
    asm volatile(
        "mma.sync.aligned.m16n8k16.row.col.f32.bf16.bf16.f32 "
        "{%0,%1,%2,%3},{%4,%5,%6,%7},{%8,%9},{%0,%1,%2,%3};"
        : "+f"(c[0]), "+f"(c[1]), "+f"(c[2]), "+f"(c[3])
        : "r"(a[0]), "r"(a[1]), "r"(a[2]), "r"(a[3]), "r"(b[0]), "r"(b[1]));
}
__device__ __forceinline__ void split_bf16(float v, __nv_bfloat16& hi, __nv_bfloat16& lo) {
    hi = __float2bfloat16(v);
    lo = __float2bfloat16(v - __bfloat162float(hi));
}

// --------------------------- x transpose -----------------------------------
__global__ void k_xT(const float* __restrict__ x) {
    __shared__ float t[32][33];
    int b = blockIdx.y;
    int ta = (blockIdx.x % 3) * 32, tb = (blockIdx.x / 3) * 32;
    t[threadIdx.y][threadIdx.x] = x[b * 9216 + (ta + threadIdx.y) * 96 + tb + threadIdx.x];
    __syncthreads();
    g_xT[b * 9216 + (tb + threadIdx.y) * 96 + ta + threadIdx.x] = t[threadIdx.x][threadIdx.y];
}

// --------------------------- stage A: from_s2 ------------------------------
__global__ void k_from_s2(const float* __restrict__ from_s2) {
    int m = blockIdx.x, b = blockIdx.y, t = threadIdx.x;
    const float* fr = from_s2 + (size_t)m * 9216;
    const float* xb = g_xT + (size_t)b * 9216;
    float acc = 0.f;
    for (int idx = t; idx < 9216; idx += 128) acc += fr[idx] * xb[idx];
    __shared__ float red[128];
    red[t] = acc;
    __syncthreads();
    for (int s = 64; s > 0; s >>= 1) {
        if (t < s) red[t] += red[t + s];
        __syncthreads();
    }
    if (t == 0) g_c[b * 121 + m] = red[0];
}

// --------------------------- stage B: psi1 ---------------------------------
__global__ void k_psi1(const float* __restrict__ Yk1, const float* __restrict__ w1) {
    int j = blockIdx.x, m = threadIdx.x;
    if (m < 121) {
        float acc = 0.f;
        for (int p = 0; p < 24; p++) acc += Yk1[p * 121 + m] * w1[j * 24 + p];
        g_psi1[j * 121 + m] = acc * 0.20412414523193154f;
    }
}

// --------------------------- stage C: h1 (fp32) ----------------------------
// h1[bj, off_l + i*k + j] = psi1-index i, c-index j:
// value = c[b, l*l + j] * psi1[f, l*l + i]
__global__ void k_h1() {
    int bj = blockIdx.x;
    int b = bj / 20, f = bj - b * 20;
    const float* cb = g_c + b * 121;
    const float* pj = g_psi1 + f * 121;
    float* out = g_h1 + (size_t)bj * 1771;
    for (int cidx = threadIdx.x; cidx < 1771; cidx += blockDim.x) {
        int l = 0;
        while (OFF1c[l + 1] <= cidx) l++;
        int k = 2 * l + 1;
        int local = cidx - OFF1c[l];
        int i = local / k;
        int j = local - i * k;
        out[cidx] = cb[l * l + j] * pj[l * l + i];
    }
}

// ================== separable SO(3) synthesis (replaces GEMM1) ==============
// g(a,b,g) = sum_l sqrt(2l+1) sum_{ij} H^l_ij [Rz(a) d^l(b) Rz(g)]_ij
// Rz(t)_{u,u} = cos(u t), Rz(t)_{u,-u} = sin(u t)  (signed index u).
// Steps per (b,f), per gamma gi:
//   W^l_{pq} = cos(q*g) H_{pq} + sin(q*g) H_{p,-q}
//   R_p(b)  = sum_{l>=|p|} dot(dtab[b][row p of l], W[row p of l])
//   R2_p(b) = sum_{l>=|p|} dot(dtab[b][row p of l], W[row -p of l])
// then g(a,b,gi) = sum_p cos(p a) R_p - sin(p a) R2_p.
// dtab rows = D1_to rows b*40 (a=g=0 grid points) = sqrt(2l+1) d^l(beta).
static const int SYN_SMEM = (20 * 1771 + 1771 + 1771 + 20 * 840 + 80) * 4;  // 223368 B

__global__ void __launch_bounds__(256, 1) k_syn(const float* __restrict__ D1_to) {
    extern __shared__ float ss[];
    float* dtab = ss;                  // [20][1771]
    float* H    = dtab + 20 * 1771;    // [1771]
    float* W    = H + 1771;            // [1771]
    float* Rbuf = W + 1771;            // [20 gil][840]  (840 = 20 beta * 21 pi * 2)
    float* ctab = Rbuf + 20 * 840;     // [40]
    float* stab = ctab + 40;           // [40]
    const int t = threadIdx.x;
    const int bj = blockIdx.x;

    if (t < 40) {
        float ang = 6.283185307179586f * (float)t / 40.f;
        ctab[t] = cosf(ang);
        stab[t] = sinf(ang);
    }
    for (int i = t; i < 1771; i += 256) H[i] = g_h1[(size_t)bj * 1771 + i];
    for (int i = t; i < 20 * 1771; i += 256) {
        int be = i / 1771, c = i - be * 1771;
        dtab[i] = D1_to[(size_t)(be * 40) * 1771 + c];
    }
    // per-thread decode of owned coefficient indices (7 max)
    int myq[7], mymir[7];
    {
        int n = 0;
        for (int cidx = t; cidx < 1771; cidx += 256, n++) {
            int l = 0;
            while (OFF1c[l + 1] <= cidx) l++;
            int k = 2 * l + 1;
            int local = cidx - OFF1c[l];
            int i = local / k;
            int j = local - i * k;
            myq[n] = j - l;
            mymir[n] = OFF1c[l] + i * k + (2 * l - j);
        }
    }
    __syncthreads();

    for (int half = 0; half < 2; half++) {
        for (int gil = 0; gil < 20; gil++) {
            int gi = half * 20 + gil;
            // W step
            {
                int n = 0;
                for (int cidx = t; cidx < 1771; cidx += 256, n++) {
                    int idx = ((myq[n] * gi) % 40 + 40) % 40;
                    W[cidx] = ctab[idx] * H[cidx] + stab[idx] * H[mymir[n]];
                }
            }
            __syncthreads();
            // R step: 840 outputs = (beta, pi, isR2)
            for (int o = t; o < 840; o += 256) {
                int be = o / 42, r = o - be * 42;
                int pi = r >> 1, isR2 = r & 1;
                int p = pi - 10;
                int ap = p < 0 ? -p : p;
                int pw = isR2 ? -p : p;
                float acc = 0.f;
                const float* drow = dtab + be * 1771;
                for (int l = ap; l <= 10; l++) {
                    int k = 2 * l + 1;
                    int rowD = OFF1c[l] + (p + l) * k;
                    int rowW = OFF1c[l] + (pw + l) * k;
                    for (int j = 0; j < k; j++)
                        acc += drow[rowD + j] * W[rowW + j];
                }
                Rbuf[gil * 840 + o] = acc;
            }
            __syncthreads();
        }
        // output for this half: tasks o = be*40 + a (beta-major for R broadcast)
        for (int o = t; o < 800; o += 256) {
            int be = o / 40, a = o - be * 40;
            float cc[21], sc[21];
#pragma unroll
            for (int pi = 0; pi <= 20; pi++) {
                int p = pi - 10;
                int idx = ((p * a) % 40 + 40) % 40;
                cc[pi] = ctab[idx];
                sc[pi] = stab[idx];
            }
            int ncol0 = (a * 20 + be) * 40 + half * 20;
            __nv_bfloat16* ghi = g_Gb + (size_t)bj * 64000 + ncol0;
            __nv_bfloat16* glo = ghi + 32000;
            for (int g2 = 0; g2 < 10; g2++) {
                __nv_bfloat162 hv, lv;
#pragma unroll
                for (int half2 = 0; half2 < 2; half2++) {
                    int gil = g2 * 2 + half2;
                    const float* rr = Rbuf + gil * 840 + be * 42;
                    float gsum = 0.f;
#pragma unroll
                    for (int pi = 0; pi <= 20; pi++)
                        gsum += cc[pi] * rr[pi * 2] - sc[pi] * rr[pi * 2 + 1];
                    float v = fmaxf(gsum, 0.f) * ACT_CST;
                    __nv_bfloat16 h, l;
                    split_bf16(v, h, l);
                    if (half2 == 0) { hv.x = h; lv.x = l; }
                    else            { hv.y = h; lv.y = l; }
                }
                ((__nv_bfloat162*)ghi)[g2] = hv;
                ((__nv_bfloat162*)glo)[g2] = lv;
            }
        }
        __syncthreads();
    }
}

// --------------------------- weight splits ---------------------------------
__global__ void k_splitF(const float* __restrict__ F1_from) {
    int n = blockIdx.x;
    __nv_bfloat16* o = g_Fb + (size_t)n * 64000;
    for (int k = threadIdx.x; k < 32000; k += blockDim.x) {
        float v = (n < 286) ? F1_from[(size_t)n * 32000 + k] : 0.f;
        __nv_bfloat16 hi, lo;
        split_bf16(v, hi, lo);
        o[k] = hi;
        o[32000 + k] = lo;
    }
}
__global__ void k_splitD2(const float* __restrict__ D2_to) {
    int n = blockIdx.x;
    __nv_bfloat16* o = g_D2b + (size_t)n * 576;
    for (int k = threadIdx.x; k < 288; k += blockDim.x) {
        float v = (k < 286) ? D2_to[(size_t)n * 286 + k] : 0.f;
        __nv_bfloat16 hi, lo;
        split_bf16(v, hi, lo);
        o[k] = hi;
        o[288 + k] = lo;
    }
}

// --------------------------- stage F: psi2 ---------------------------------
__global__ void k_psi2(const float* __restrict__ Dk2, const float* __restrict__ w2) {
    int ij = blockIdx.x;
    int c = threadIdx.x;
    if (c < 286) {
        const float* w = w2 + ij * 168;
        float acc = 0.f;
        for (int n = 0; n < 168; n++) acc += Dk2[n * 286 + c] * w[n];
        g_psi2[ij * 286 + c] = acc * 0.07715167498104596f;
    }
}

// --------------------------- zero init -------------------------------------
__global__ void k_zero(float* __restrict__ out) {
    int i = blockIdx.x * blockDim.x + threadIdx.x;
    if (i < 640 * 286) g_h2[i] = 0.f;
    if (i < 1280) out[i] = 0.f;
}

// ======================= bf16x3 mma GEMM (modes 1,2) ========================
// MODE 1 (GEMM2): A=g_Gb  Kp=32000, B=g_Fb,  split-K=10, ep: atomicAdd g_h2
// MODE 2 (GEMM3): A=g_h3b Kp=288,   B=g_D2b, ep: relu*ACT*wvec reduce -> out
#define PITCH 40
#define MATSZ (128 * PITCH)
#define STAGE (4 * MATSZ)
static const int SMEM1_BYTES = 2 * STAGE * 2;  // 81920

__device__ __forceinline__ void ld_stage(uint32_t sb, int t,
                                         const __nv_bfloat16* A0,
                                         const __nv_bfloat16* B0,
                                         int Kp, int stage, int kc) {
    uint32_t st = sb + (uint32_t)stage * (STAGE * 2);
    const size_t stride = 2 * (size_t)Kp;
    const __nv_bfloat16* srcs[4] = {A0 + kc * 32, A0 + Kp + kc * 32,
                                    B0 + kc * 32, B0 + Kp + kc * 32};
#pragma unroll
    for (int mtx = 0; mtx < 4; mtx++) {
        uint32_t base = st + (uint32_t)mtx * (MATSZ * 2);
        const __nv_bfloat16* src = srcs[mtx];
#pragma unroll
        for (int i = 0; i < 4; i++) {
            int idx = t + 128 * i;
            int row = idx >> 2, ch = idx & 3;
            cp16(base + row * (PITCH * 2) + ch * 16, src + row * stride + ch * 8);
        }
    }
    CP_COMMIT();
}

template <int MODE>
__global__ void __launch_bounds__(128, 2) mma_gemm(const float* __restrict__ wvec,
                                                   float* __restrict__ outv) {
    constexpr int KP = (MODE == 1) ? 32000 : 288;
    constexpr int CH = (MODE == 1) ? 100 : 9;

    extern __shared__ __align__(16) __nv_bfloat16 sm[];
    uint32_t sb = smem_u32(sm);
    const int t = threadIdx.x;
    const int warp = t >> 5, lane = t & 31;
    const int wm = warp & 1, wn = warp >> 1;
    const int g = lane >> 2, tg = lane & 3;
    const int m0 = blockIdx.x * 128;
    const int n0 = blockIdx.y * 128;
    const int kbase = (MODE == 1) ? (int)blockIdx.z * 3200 : 0;

    const __nv_bfloat16* A0 = ((MODE == 1) ? g_Gb : g_h3b) + (size_t)m0 * (2 * KP) + kbase;
    const __nv_bfloat16* B0 = ((MODE == 1) ? g_Fb : g_D2b) + (size_t)n0 * (2 * KP) + kbase;

    float acc[4][8][4];
#pragma unroll
    for (int a = 0; a < 4; a++)
#pragma unroll
        for (int b = 0; b < 8; b++)
#pragma unroll
            for (int c = 0; c < 4; c++) acc[a][b][c] = 0.f;

    ld_stage(sb, t, A0, B0, KP, 0, 0);
    ld_stage(sb, t, A0, B0, KP, 1, 1);

    for (int kc = 0; kc < CH; kc++) {
        int buf = kc & 1;
        if (kc < CH - 1) CP_WAIT1(); else CP_WAIT0();
        __syncthreads();

        const __nv_bfloat16* Ah = sm + buf * STAGE;
        const __nv_bfloat16* Al = Ah + MATSZ;
        const __nv_bfloat16* Bh = Al + MATSZ;
        const __nv_bfloat16* Bl = Bh + MATSZ;

#pragma unroll
        for (int s = 0; s < 2; s++) {
            const int k0 = s * 16 + tg * 2;
            uint32_t ah[4][4], al[4][4];
#pragma unroll
            for (int mt = 0; mt < 4; mt++) {
                int r = wm * 64 + mt * 16 + g;
                ah[mt][0] = *(const uint32_t*)&Ah[r * PITCH + k0];
                ah[mt][1] = *(const uint32_t*)&Ah[(r + 8) * PITCH + k0];
                ah[mt][2] = *(const uint32_t*)&Ah[r * PITCH + k0 + 8];
                ah[mt][3] = *(const uint32_t*)&Ah[(r + 8) * PITCH + k0 + 8];
                al[mt][0] = *(const uint32_t*)&Al[r * PITCH + k0];
                al[mt][1] = *(const uint32_t*)&Al[(r + 8) * PITCH + k0];
                al[mt][2] = *(const uint32_t*)&Al[r * PITCH + k0 + 8];
                al[mt][3] = *(const uint32_t*)&Al[(r + 8) * PITCH + k0 + 8];
            }
#pragma unroll
            for (int nt = 0; nt < 8; nt++) {
                int r = wn * 64 + nt * 8 + g;
                uint32_t bh[2], bl[2];
                bh[0] = *(const uint32_t*)&Bh[r * PITCH + k0];
                bh[1] = *(const uint32_t*)&Bh[r * PITCH + k0 + 8];
                bl[0] = *(const uint32_t*)&Bl[r * PITCH + k0];
                bl[1] = *(const uint32_t*)&Bl[r * PITCH + k0 + 8];
#pragma unroll
                for (int mt = 0; mt < 4; mt++) {
                    mma16816(acc[mt][nt], ah[mt], bh);
                    mma16816(acc[mt][nt], ah[mt], bl);
                    mma16816(acc[mt][nt], al[mt], bh);
                }
            }
        }
        __syncthreads();
        if (kc + 2 < CH) ld_stage(sb, t, A0, B0, KP, buf, kc + 2);
    }

    if (MODE == 1) {
#pragma unroll
        for (int mt = 0; mt < 4; mt++) {
#pragma unroll
            for (int nt = 0; nt < 8; nt++) {
                int row = m0 + wm * 64 + mt * 16 + g;
                int col = n0 + wn * 64 + nt * 8 + tg * 2;
#pragma unroll
                for (int half = 0; half < 2; half++) {
                    int r = row + 8 * half;
                    if (col < 286) atomicAdd(&g_h2[r * 286 + col], acc[mt][nt][2 * half]);
                    if (col + 1 < 286) atomicAdd(&g_h2[r * 286 + col + 1], acc[mt][nt][2 * half + 1]);
                }
            }
        }
    } else {
#pragma unroll
        for (int mt = 0; mt < 4; mt++) {
            float s0 = 0.f, s1 = 0.f;
#pragma unroll
            for (int nt = 0; nt < 8; nt++) {
                int col = n0 + wn * 64 + nt * 8 + tg * 2;
                float w0 = wvec[col], w1 = wvec[col + 1];
                s0 += fmaxf(acc[mt][nt][0], 0.f) * w0 + fmaxf(acc[mt][nt][1], 0.f) * w1;
                s1 += fmaxf(acc[mt][nt][2], 0.f) * w0 + fmaxf(acc[mt][nt][3], 0.f) * w1;
            }
            s0 += __shfl_xor_sync(0xFFFFFFFF, s0, 1);
            s0 += __shfl_xor_sync(0xFFFFFFFF, s0, 2);
            s1 += __shfl_xor_sync(0xFFFFFFFF, s1, 1);
            s1 += __shfl_xor_sync(0xFFFFFFFF, s1, 2);
            if (tg == 0) {
                int row = m0 + wm * 64 + mt * 16 + g;
                atomicAdd(&outv[row], s0 * ACT_CST);
                atomicAdd(&outv[row + 8], s1 * ACT_CST);
            }
        }
    }
}

// --------------------------- stage G: conv2 --------------------------------
__global__ void __launch_bounds__(320) k_conv2() {
    int bj = blockIdx.x;
    int b = bj / 40, j = bj - b * 40;
    __shared__ float h2s[20 * 286];
    __shared__ float ps[20 * 286];
    for (int idx = threadIdx.x; idx < 20 * 286; idx += blockDim.x) {
        int i = idx / 286, c = idx - i * 286;
        h2s[idx] = g_h2[(b * 20 + i) * 286 + c];
        ps[idx]  = g_psi2[(i * 40 + j) * 286 + c];
    }
    __syncthreads();
    int c = threadIdx.x;
    if (c < 288) {
        float val = 0.f;
        if (c < 286) {
            int l = 0;
            while (OFF2c[l + 1] <= c) l++;
            int k = 2 * l + 1;
            int local = c - OFF2c[l];
            int v = local / k;
            int m = local - v * k;
            int off = OFF2c[l];
            float acc = 0.f;
            for (int i = 0; i < 20; i++) {
                const float* hr = h2s + i * 286 + off;
                const float* pr = ps + i * 286 + off;
                for (int u = 0; u < k; u++)
                    acc = fmaf(hr[u * k + m], pr[u * k + v], acc);
            }
            val = acc * (1.0f / sqrtf(20.0f * (float)k));
        }
        __nv_bfloat16 hi, lo;
        split_bf16(val, hi, lo);
        g_h3b[bj * 576 + c] = hi;
        g_h3b[bj * 576 + 288 + c] = lo;
    }
}

// --------------------------- launcher --------------------------------------
extern "C" void kernel_launch(void* const* d_in, const int* in_sizes, int n_in,
                              void* d_out, int out_size) {
    const float* x       = (const float*)d_in[0];
    const float* w1      = (const float*)d_in[1];
    const float* w2      = (const float*)d_in[2];
    const float* Yk1     = (const float*)d_in[3];
    const float* Dk2     = (const float*)d_in[4];
    const float* from_s2 = (const float*)d_in[5];
    const float* D1_to   = (const float*)d_in[6];
    const float* F1_from = (const float*)d_in[7];
    const float* D2_to   = (const float*)d_in[8];
    const float* F2_from = (const float*)d_in[9];
    float* out = (float*)d_out;
    (void)in_sizes; (void)n_in; (void)out_size;

    cudaFuncSetAttribute(k_syn, cudaFuncAttributeMaxDynamicSharedMemorySize, SYN_SMEM);
    cudaFuncSetAttribute(mma_gemm<1>, cudaFuncAttributeMaxDynamicSharedMemorySize, SMEM1_BYTES);
    cudaFuncSetAttribute(mma_gemm<2>, cudaFuncAttributeMaxDynamicSharedMemorySize, SMEM1_BYTES);

    k_zero<<<(640 * 286 + 255) / 256, 256>>>(out);
    k_xT<<<dim3(9, 32), dim3(32, 32)>>>(x);
    k_from_s2<<<dim3(121, 32), 128>>>(from_s2);
    k_psi1<<<20, 128>>>(Yk1, w1);
    k_h1<<<640, 256>>>();
    // separable SO(3) synthesis: replaces GEMM1 + D1_to split
    k_syn<<<640, 256, SYN_SMEM>>>(D1_to);
    k_splitF<<<384, 256>>>(F1_from);
    k_splitD2<<<6912, 128>>>(D2_to);
    k_psi2<<<800, 320>>>(Dk2, w2);
    // GEMM2: grid -> Fourier, split-K = 10
    mma_gemm<1><<<dim3(5, 3, 10), 128, SMEM1_BYTES>>>(nullptr, nullptr);
    k_conv2<<<1280, 320>>>();
    // GEMM3: final activation + projection, fused reduce into out
    mma_gemm<2><<<dim3(10, 54, 1), 128, SMEM1_BYTES>>>(F2_from, out);
}